// round 3
// baseline (speedup 1.0000x reference)
#include <cuda_runtime.h>
#include <math.h>
#include <stdint.h>

// ---------------- problem constants ----------------
#define B_    4
#define S_    256
#define BS_   1024          // B*S
#define NN    500           // nodes
#define NPAD  512
#define FF    32
#define DD    64
#define GDCOL 65536         // BS_*DD
#define I3D   192
#define KIN   32000
#define SPLITK 25
#define KCH_L  1280         // 32000/25

// ---------------- device scratch (static zero-init; pads never written) ----------------
__device__ __align__(16) float g_X[(size_t)NPAD * BS_ * DD];
__device__ __align__(16) float g_Y[(size_t)NPAD * BS_ * DD];
__device__ __align__(16) float g_flat[(size_t)BS_ * KIN];
__device__ __align__(16) float g_adjT[NPAD * NPAD];
__device__ __align__(16) float g_part_l[SPLITK * BS_ * I3D];
__device__ __align__(16) float g_part_m[SPLITK * 80 * I3D];
__device__ __align__(16) float g_part_s[SPLITK * 40 * I3D];
__device__ __align__(16) float g_xp_l[BS_ * I3D];
__device__ __align__(16) float g_xp_m[80 * I3D];
__device__ __align__(16) float g_xp_s[40 * I3D];
__device__ __align__(16) float g_hcat[4 * I3D];

__device__ __forceinline__ float gelu_f(float x) {
    return 0.5f * x * (1.0f + erff(x * 0.7071067811865476f));
}
__device__ __forceinline__ float sigm_f(float x) {
    return 1.0f / (1.0f + expf(-x));
}

// =====================================================================
// 1) input projection: X[n][bs][d] = gelu(sum_f x[bs][n][f]*ipW[d][f] + b[d])
//    warp per token, 16 token-groups per block
// =====================================================================
__global__ __launch_bounds__(256) void k_input_proj(
    const float* __restrict__ x, const float* __restrict__ ipW, const float* __restrict__ ipb)
{
    __shared__ float Wt[FF][DD];   // Wt[f][d]
    __shared__ float sb[DD];
    int tid = threadIdx.x;
    for (int q = tid; q < FF * DD; q += 256) {
        int d = q >> 5, f = q & 31;          // ipW row-major [d][f]
        Wt[f][d] = ipW[q];
    }
    if (tid < DD) sb[tid] = ipb[tid];
    __syncthreads();
    int warp = tid >> 5, lane = tid & 31;
    for (int it = 0; it < 16; it++) {
        int row = (blockIdx.x * 16 + it) * 8 + warp;   // row = bs*500+n, < 512000
        float xv = x[(size_t)row * FF + lane];
        float a0 = sb[lane], a1 = sb[lane + 32];
#pragma unroll
        for (int f = 0; f < FF; f++) {
            float xf = __shfl_sync(0xffffffffu, xv, f);
            a0 += xf * Wt[f][lane];
            a1 += xf * Wt[f][lane + 32];
        }
        int bs = row / NN, n = row - bs * NN;
        size_t base = ((size_t)n * BS_ + bs) * DD;
        g_X[base + lane]      = gelu_f(a0);
        g_X[base + lane + 32] = gelu_f(a1);
    }
}

// =====================================================================
// 2) adjacency: adjT[m][n] = softmax_over_m((from[n].to[m]) * 2)
// =====================================================================
__global__ __launch_bounds__(256) void k_adj(
    const float* __restrict__ fe, const float* __restrict__ te)
{
    __shared__ float fl[32];
    __shared__ float lg[NN];
    __shared__ float redm[8], reds[8];
    int n = blockIdx.x, tid = threadIdx.x;
    int lane = tid & 31, warp = tid >> 5;
    if (tid < 32) fl[tid] = fe[n * 32 + tid];
    __syncthreads();

    float lmax = -1e30f;
    for (int m = tid; m < NN; m += 256) {
        float s = 0.f;
#pragma unroll
        for (int f = 0; f < 32; f++) s += fl[f] * te[m * 32 + f];
        s *= 2.0f;                 // divide by TEMP=0.5
        lg[m] = s;
        lmax = fmaxf(lmax, s);
    }
#pragma unroll
    for (int o = 16; o; o >>= 1) lmax = fmaxf(lmax, __shfl_xor_sync(0xffffffffu, lmax, o));
    if (lane == 0) redm[warp] = lmax;
    __syncthreads();
    float mx = redm[0];
#pragma unroll
    for (int w = 1; w < 8; w++) mx = fmaxf(mx, redm[w]);

    float lsum = 0.f;
    for (int m = tid; m < NN; m += 256) {
        float e = expf(lg[m] - mx);
        lg[m] = e;
        lsum += e;
    }
#pragma unroll
    for (int o = 16; o; o >>= 1) lsum += __shfl_xor_sync(0xffffffffu, lsum, o);
    if (lane == 0) reds[warp] = lsum;
    __syncthreads();
    float tot = 0.f;
#pragma unroll
    for (int w = 0; w < 8; w++) tot += reds[w];
    float inv = 1.0f / tot;
    for (int m = tid; m < NPAD; m += 256)
        g_adjT[m * NPAD + n] = (m < NN) ? lg[m] * inv : 0.f;
    // columns n in [500,512) of g_adjT are never written -> stay statically zero
}

// =====================================================================
// 3) aggregation SGEMM: Y = adjT(512x512, pad-zero) @ X(512x65536)
//    128x128x8 tiles, 8x8 per thread, double-buffered
// =====================================================================
__global__ __launch_bounds__(256, 2) void k_agg()
{
    __shared__ __align__(16) float As[2][8][128];
    __shared__ __align__(16) float Bs[2][8][128];
    int tid = threadIdx.x;
    int m0 = blockIdx.y * 128;
    int n0 = blockIdx.x * 128;
    int a_r = tid >> 1;              // 0..127
    int a_k = (tid & 1) * 4;         // 0,4
    int b_k = tid >> 5;              // 0..7
    int b_c = (tid & 31) * 4;        // 0..124
    int ty = tid >> 4, tx = tid & 15;

    float acc[8][8];
#pragma unroll
    for (int i = 0; i < 8; i++)
#pragma unroll
        for (int j = 0; j < 8; j++) acc[i][j] = 0.f;

    const float* A = g_adjT;
    const float* Bm = g_X;
    const int NK = NPAD / 8;   // 64

    float4 aReg = *(const float4*)&A[(m0 + a_r) * NPAD + a_k];
    float4 bReg = *(const float4*)&Bm[(size_t)b_k * GDCOL + n0 + b_c];
    As[0][a_k + 0][a_r] = aReg.x; As[0][a_k + 1][a_r] = aReg.y;
    As[0][a_k + 2][a_r] = aReg.z; As[0][a_k + 3][a_r] = aReg.w;
    *(float4*)&Bs[0][b_k][b_c] = bReg;
    __syncthreads();

    for (int kt = 0; kt < NK; kt++) {
        int cur = kt & 1, nxt = cur ^ 1;
        if (kt + 1 < NK) {
            int k0 = (kt + 1) * 8;
            aReg = *(const float4*)&A[(m0 + a_r) * NPAD + k0 + a_k];
            bReg = *(const float4*)&Bm[(size_t)(k0 + b_k) * GDCOL + n0 + b_c];
        }
#pragma unroll
        for (int k = 0; k < 8; k++) {
            float4 av0 = *(const float4*)&As[cur][k][ty * 8];
            float4 av1 = *(const float4*)&As[cur][k][ty * 8 + 4];
            float4 bv0 = *(const float4*)&Bs[cur][k][tx * 8];
            float4 bv1 = *(const float4*)&Bs[cur][k][tx * 8 + 4];
            float af[8] = {av0.x, av0.y, av0.z, av0.w, av1.x, av1.y, av1.z, av1.w};
            float bf[8] = {bv0.x, bv0.y, bv0.z, bv0.w, bv1.x, bv1.y, bv1.z, bv1.w};
#pragma unroll
            for (int i = 0; i < 8; i++)
#pragma unroll
                for (int j = 0; j < 8; j++)
                    acc[i][j] += af[i] * bf[j];
        }
        if (kt + 1 < NK) {
            As[nxt][a_k + 0][a_r] = aReg.x; As[nxt][a_k + 1][a_r] = aReg.y;
            As[nxt][a_k + 2][a_r] = aReg.z; As[nxt][a_k + 3][a_r] = aReg.w;
            *(float4*)&Bs[nxt][b_k][b_c] = bReg;
        }
        __syncthreads();
    }

#pragma unroll
    for (int i = 0; i < 8; i++) {
        size_t rb = (size_t)(m0 + ty * 8 + i) * GDCOL + n0 + tx * 8;
        float4 v0 = make_float4(acc[i][0], acc[i][1], acc[i][2], acc[i][3]);
        float4 v1 = make_float4(acc[i][4], acc[i][5], acc[i][6], acc[i][7]);
        *(float4*)&g_Y[rb]     = v0;
        *(float4*)&g_Y[rb + 4] = v1;
    }
}

// =====================================================================
// 4) per-token: h = gelu((X+Y) @ W^T + b); x' = LN(h)*g+be
//    warp per token. mode 0 -> write g_X (n-major); mode 1 -> write g_flat (bs-major)
// =====================================================================
__global__ __launch_bounds__(256) void k_token(
    const float* __restrict__ W, const float* __restrict__ bvec,
    const float* __restrict__ gvec, const float* __restrict__ bevec, int mode)
{
    __shared__ float Wt[64][65];
    __shared__ float sb[64], sg[64], sbe[64];
    int tid = threadIdx.x;
    for (int q = tid; q < 4096; q += 256) {
        int e = q >> 6, d = q & 63;
        Wt[d][e] = W[q];              // W row-major [e][d]
    }
    if (tid < 64) { sb[tid] = bvec[tid]; sg[tid] = gvec[tid]; sbe[tid] = bevec[tid]; }
    __syncthreads();
    int warp = tid >> 5, lane = tid & 31;
    for (int it = 0; it < 16; it++) {
        int tok = (blockIdx.x * 16 + it) * 8 + warp;   // tok = n*1024 + bs, < 512000
        size_t base = (size_t)tok * 64;
        float u0 = g_X[base + lane]      + g_Y[base + lane];
        float u1 = g_X[base + lane + 32] + g_Y[base + lane + 32];
        float a0 = sb[lane], a1 = sb[lane + 32];
#pragma unroll
        for (int d = 0; d < 32; d++) {
            float ud = __shfl_sync(0xffffffffu, u0, d);
            a0 += ud * Wt[d][lane];
            a1 += ud * Wt[d][lane + 32];
        }
#pragma unroll
        for (int d = 0; d < 32; d++) {
            float ud = __shfl_sync(0xffffffffu, u1, d);
            a0 += ud * Wt[d + 32][lane];
            a1 += ud * Wt[d + 32][lane + 32];
        }
        float h0 = gelu_f(a0), h1 = gelu_f(a1);
        float s = h0 + h1;
#pragma unroll
        for (int o = 16; o; o >>= 1) s += __shfl_xor_sync(0xffffffffu, s, o);
        float mu = s * (1.0f / 64.0f);
        float d0 = h0 - mu, d1 = h1 - mu;
        float v = d0 * d0 + d1 * d1;
#pragma unroll
        for (int o = 16; o; o >>= 1) v += __shfl_xor_sync(0xffffffffu, v, o);
        float inv = rsqrtf(v * (1.0f / 64.0f) + 1e-5f);
        float o0 = d0 * inv * sg[lane]      + sbe[lane];
        float o1 = d1 * inv * sg[lane + 32] + sbe[lane + 32];
        if (mode == 0) {
            g_X[base + lane]      = o0;
            g_X[base + lane + 32] = o1;
        } else {
            int m = tok >> 10, bs = tok & 1023;
            size_t ob = (size_t)bs * KIN + (size_t)m * 64;
            g_flat[ob + lane]      = o0;
            g_flat[ob + lane + 32] = o1;
        }
    }
}

// =====================================================================
// 5) GRU input projection: part[z][r][g] = sum_{k in chunk z} xflat[row(r)][k]*Wih[g][k]
//    64x64x8 tiles, split-K=25, 4x4 per thread
// =====================================================================
__global__ __launch_bounds__(256) void k_xp(
    const float* __restrict__ W, int T, int Mtot, int KCH, int sel)
{
    __shared__ float As[2][8][65];
    __shared__ float Bs[2][8][65];
    float* part = (sel == 0) ? g_part_l : (sel == 1) ? g_part_m : g_part_s;

    int tid = threadIdx.x;
    int m0 = blockIdx.x * 64;
    int n0 = blockIdx.y * 64;
    int z  = blockIdx.z;
    int kbase = z * KCH;

    int a_r = tid >> 2;            // 0..63
    int a_k = (tid & 3) * 2;       // 0,2,4,6
    int b_g = tid >> 2;
    int b_k = (tid & 3) * 2;
    int ty = tid >> 4, tx = tid & 15;

    int r = m0 + a_r;
    bool a_valid = (r < Mtot);
    const float* aptr = g_flat;    // dummy base; only dereferenced when a_valid
    if (a_valid) {
        int bb = r / T, tt = r - bb * T;
        int frow = bb * S_ + (S_ - T) + tt;
        aptr = g_flat + (size_t)frow * KIN;
    }
    const float* bptr = W + (size_t)(n0 + b_g) * KIN;

    float acc[4][4];
#pragma unroll
    for (int i = 0; i < 4; i++)
#pragma unroll
        for (int j = 0; j < 4; j++) acc[i][j] = 0.f;

    int NT = KCH / 8;
    float2 aReg = a_valid ? *(const float2*)(aptr + kbase + a_k) : make_float2(0.f, 0.f);
    float2 bReg = *(const float2*)(bptr + kbase + b_k);
    As[0][a_k][a_r] = aReg.x; As[0][a_k + 1][a_r] = aReg.y;
    Bs[0][b_k][b_g] = bReg.x; Bs[0][b_k + 1][b_g] = bReg.y;
    __syncthreads();

    for (int kt = 0; kt < NT; kt++) {
        int cur = kt & 1, nxt = cur ^ 1;
        if (kt + 1 < NT) {
            int k0 = kbase + (kt + 1) * 8;
            aReg = a_valid ? *(const float2*)(aptr + k0 + a_k) : make_float2(0.f, 0.f);
            bReg = *(const float2*)(bptr + k0 + b_k);
        }
#pragma unroll
        for (int k = 0; k < 8; k++) {
            float af[4], bf[4];
#pragma unroll
            for (int i = 0; i < 4; i++) af[i] = As[cur][k][ty * 4 + i];
#pragma unroll
            for (int j = 0; j < 4; j++) bf[j] = Bs[cur][k][tx * 4 + j];
#pragma unroll
            for (int i = 0; i < 4; i++)
#pragma unroll
                for (int j = 0; j < 4; j++)
                    acc[i][j] += af[i] * bf[j];
        }
        if (kt + 1 < NT) {
            As[nxt][a_k][a_r] = aReg.x; As[nxt][a_k + 1][a_r] = aReg.y;
            Bs[nxt][b_k][b_g] = bReg.x; Bs[nxt][b_k + 1][b_g] = bReg.y;
        }
        __syncthreads();
    }

#pragma unroll
    for (int i = 0; i < 4; i++) {
        int rr = m0 + ty * 4 + i;
        if (rr < Mtot) {
#pragma unroll
            for (int j = 0; j < 4; j++) {
                int gg = n0 + tx * 4 + j;
                part[((size_t)z * Mtot + rr) * I3D + gg] = acc[i][j];
            }
        }
    }
}

__global__ void k_xp_reduce(const float* __restrict__ bih, int Mtot, int sel)
{
    const float* part = (sel == 0) ? g_part_l : (sel == 1) ? g_part_m : g_part_s;
    float* out = (sel == 0) ? g_xp_l : (sel == 1) ? g_xp_m : g_xp_s;
    int i = blockIdx.x * 256 + threadIdx.x;
    int tot = Mtot * I3D;
    if (i >= tot) return;
    int g = i % I3D;
    float s = bih[g];
    for (int z = 0; z < SPLITK; z++) s += part[(size_t)z * tot + i];
    out[i] = s;
}

// =====================================================================
// 6) GRU recurrence: 12 blocks (gru, b), 192 threads (one per gate unit)
// =====================================================================
__global__ __launch_bounds__(192) void k_gru(
    const float* __restrict__ Whh_s, const float* __restrict__ bhh_s,
    const float* __restrict__ Whh_m, const float* __restrict__ bhh_m,
    const float* __restrict__ Whh_l, const float* __restrict__ bhh_l)
{
    int blk = blockIdx.x;          // 0..11
    int gru = blk >> 2;            // 0=s,1=m,2=l
    int b = blk & 3;
    int T = (gru == 0) ? 10 : (gru == 1) ? 20 : 256;
    const float* xp  = (gru == 0) ? g_xp_s : (gru == 1) ? g_xp_m : g_xp_l;
    const float* Whh = (gru == 0) ? Whh_s : (gru == 1) ? Whh_m : Whh_l;
    const float* bhh = (gru == 0) ? bhh_s : (gru == 1) ? bhh_m : bhh_l;
    int g = threadIdx.x;           // 0..191

    float w[64];
#pragma unroll
    for (int d = 0; d < 64; d += 4) {
        float4 v = *(const float4*)&Whh[g * 64 + d];
        w[d] = v.x; w[d + 1] = v.y; w[d + 2] = v.z; w[d + 3] = v.w;
    }
    float bh = bhh[g];

    __shared__ float h_sh[64], r_sh[64], z_sh[64], n_sh[64];
    if (g < 64) h_sh[g] = 0.f;
    __syncthreads();

    const float* xpb = xp + (size_t)b * T * I3D;
    for (int t = 0; t < T; t++) {
        float a0 = 0.f, a1 = 0.f, a2 = 0.f, a3 = 0.f;
#pragma unroll
        for (int d = 0; d < 64; d += 4) {
            a0 += w[d]     * h_sh[d];
            a1 += w[d + 1] * h_sh[d + 1];
            a2 += w[d + 2] * h_sh[d + 2];
            a3 += w[d + 3] * h_sh[d + 3];
        }
        float gh = bh + ((a0 + a1) + (a2 + a3));
        float xv = xpb[t * I3D + g];
        if (g < 64) {
            r_sh[g] = sigm_f(xv + gh);
        } else if (g < 128) {
            z_sh[g - 64] = sigm_f(xv + gh);
        }
        __syncthreads();
        if (g >= 128) {
            n_sh[g - 128] = tanhf(xv + r_sh[g - 128] * gh);
        }
        __syncthreads();
        if (g < 64) {
            float zz = z_sh[g], nn = n_sh[g];
            h_sh[g] = (1.f - zz) * nn + zz * h_sh[g];
        }
        __syncthreads();
    }
    if (g < 64) g_hcat[b * I3D + gru * 64 + g] = h_sh[g];
}

// =====================================================================
// 7) head: h1 = gelu(hcat @ W1^T + b1); out = h1 @ W2^T + b2
// =====================================================================
__global__ __launch_bounds__(256) void k_head(
    const float* __restrict__ W1, const float* __restrict__ b1,
    const float* __restrict__ W2, const float* __restrict__ b2,
    float* __restrict__ out)
{
    __shared__ float hc[4 * I3D];
    __shared__ float h1[4 * 64];
    int t = threadIdx.x;
    for (int i = t; i < 4 * I3D; i += 256) hc[i] = g_hcat[i];
    __syncthreads();
    {
        int b = t >> 6, e = t & 63;
        float a = b1[e];
#pragma unroll 8
        for (int gg = 0; gg < I3D; gg++) a += hc[b * I3D + gg] * W1[e * I3D + gg];
        h1[b * 64 + e] = gelu_f(a);
    }
    __syncthreads();
    for (int q = t; q < 4 * NN; q += 256) {
        int b = q / NN, n = q - b * NN;
        float a = b2[n];
#pragma unroll 8
        for (int e = 0; e < 64; e++) a += h1[b * 64 + e] * W2[n * 64 + e];
        out[b * NN + n] = a;
    }
}

// =====================================================================
// launcher
// =====================================================================
extern "C" void kernel_launch(void* const* d_in, const int* in_sizes, int n_in,
                              void* d_out, int out_size)
{
    const float* x     = (const float*)d_in[0];
    const float* ipW   = (const float*)d_in[1];
    const float* ipb   = (const float*)d_in[2];
    const float* fe    = (const float*)d_in[3];
    const float* te    = (const float*)d_in[4];
    const float* glW   = (const float*)d_in[5];
    const float* glb   = (const float*)d_in[6];
    const float* glg   = (const float*)d_in[7];
    const float* glbe  = (const float*)d_in[8];
    const float* Wih_s = (const float*)d_in[9];
    const float* Whh_s = (const float*)d_in[10];
    const float* bih_s = (const float*)d_in[11];
    const float* bhh_s = (const float*)d_in[12];
    const float* Wih_m = (const float*)d_in[13];
    const float* Whh_m = (const float*)d_in[14];
    const float* bih_m = (const float*)d_in[15];
    const float* bhh_m = (const float*)d_in[16];
    const float* Wih_l = (const float*)d_in[17];
    const float* Whh_l = (const float*)d_in[18];
    const float* bih_l = (const float*)d_in[19];
    const float* bhh_l = (const float*)d_in[20];
    const float* dhW1  = (const float*)d_in[21];
    const float* dhb1  = (const float*)d_in[22];
    const float* dhW2  = (const float*)d_in[23];
    const float* dhb2  = (const float*)d_in[24];
    float* out = (float*)d_out;

    k_input_proj<<<4000, 256>>>(x, ipW, ipb);
    k_adj<<<NN, 256>>>(fe, te);

    // layer 0
    k_agg<<<dim3(GDCOL / 128, 4), 256>>>();
    k_token<<<4000, 256>>>(glW, glb, glg, glbe, 0);
    // layer 1
    k_agg<<<dim3(GDCOL / 128, 4), 256>>>();
    k_token<<<4000, 256>>>(glW + 4096, glb + 64, glg + 64, glbe + 64, 1);

    // GRU input projections (split-K)
    k_xp<<<dim3(16, 3, SPLITK), 256>>>(Wih_l, 256, 1024, KCH_L, 0);
    k_xp<<<dim3(2, 3, SPLITK), 256>>>(Wih_m, 20, 80, KCH_L, 1);
    k_xp<<<dim3(1, 3, SPLITK), 256>>>(Wih_s, 10, 40, KCH_L, 2);
    k_xp_reduce<<<(1024 * I3D + 255) / 256, 256>>>(bih_l, 1024, 0);
    k_xp_reduce<<<(80 * I3D + 255) / 256, 256>>>(bih_m, 80, 1);
    k_xp_reduce<<<(40 * I3D + 255) / 256, 256>>>(bih_s, 40, 2);

    k_gru<<<12, 192>>>(Whh_s, bhh_s, Whh_m, bhh_m, Whh_l, bhh_l);
    k_head<<<1, 256>>>(dhW1, dhb1, dhW2, dhb2, out);
}

// round 4
// speedup vs baseline: 1.0988x; 1.0988x over previous
#include <cuda_runtime.h>
#include <math.h>
#include <stdint.h>

// ---------------- problem constants ----------------
#define B_    4
#define S_    256
#define BS_   1024          // B*S
#define NN    500           // nodes
#define NPAD  512
#define FF    32
#define DD    64
#define GDCOL 65536         // BS_*DD
#define I3D   192
#define KIN   32000
#define SPLITK 25
#define KCH_L  1280         // 32000/25

// ---------------- device scratch (static zero-init; pads never written) ----------------
__device__ __align__(16) float g_X[(size_t)NPAD * BS_ * DD];
__device__ __align__(16) float g_Y[(size_t)NPAD * BS_ * DD];
__device__ __align__(16) float g_flat[(size_t)BS_ * KIN];
__device__ __align__(16) float g_adjT[NPAD * NPAD];
__device__ __align__(16) float g_part_l[SPLITK * BS_ * I3D];
__device__ __align__(16) float g_part_m[SPLITK * 80 * I3D];
__device__ __align__(16) float g_part_s[SPLITK * 40 * I3D];
__device__ __align__(16) float g_xp_l[BS_ * I3D];
__device__ __align__(16) float g_xp_m[80 * I3D];
__device__ __align__(16) float g_xp_s[40 * I3D];
__device__ __align__(16) float g_hcat[4 * I3D];

__device__ __forceinline__ float gelu_f(float x) {
    return 0.5f * x * (1.0f + erff(x * 0.7071067811865476f));
}
__device__ __forceinline__ float sigm_f(float x) {
    return 1.0f / (1.0f + expf(-x));
}

// tf32 split helpers
__device__ __forceinline__ uint32_t to_tf32(float v) {
    uint32_t r;
    asm("cvt.rna.tf32.f32 %0, %1;" : "=r"(r) : "f"(v));
    return r;
}
__device__ __forceinline__ void split_tf32(float v, float& hi, float& lo) {
    uint32_t h = to_tf32(v);
    hi = __uint_as_float(h);
    lo = __uint_as_float(to_tf32(v - hi));
}
__device__ __forceinline__ void mma_tf32(float* c, const uint32_t* a, const uint32_t* b) {
    asm volatile(
        "mma.sync.aligned.m16n8k8.row.col.f32.tf32.tf32.f32 "
        "{%0,%1,%2,%3}, {%4,%5,%6,%7}, {%8,%9}, {%0,%1,%2,%3};"
        : "+f"(c[0]), "+f"(c[1]), "+f"(c[2]), "+f"(c[3])
        : "r"(a[0]), "r"(a[1]), "r"(a[2]), "r"(a[3]), "r"(b[0]), "r"(b[1]));
}

// =====================================================================
// 1) input projection: X[n][bs][d] = gelu(sum_f x[bs][n][f]*ipW[d][f] + b[d])
// =====================================================================
__global__ __launch_bounds__(256) void k_input_proj(
    const float* __restrict__ x, const float* __restrict__ ipW, const float* __restrict__ ipb)
{
    __shared__ float Wt[FF][DD];   // Wt[f][d]
    __shared__ float sb[DD];
    int tid = threadIdx.x;
    for (int q = tid; q < FF * DD; q += 256) {
        int d = q >> 5, f = q & 31;          // ipW row-major [d][f]
        Wt[f][d] = ipW[q];
    }
    if (tid < DD) sb[tid] = ipb[tid];
    __syncthreads();
    int warp = tid >> 5, lane = tid & 31;
    for (int it = 0; it < 16; it++) {
        int row = (blockIdx.x * 16 + it) * 8 + warp;   // row = bs*500+n, < 512000
        float xv = x[(size_t)row * FF + lane];
        float a0 = sb[lane], a1 = sb[lane + 32];
#pragma unroll
        for (int f = 0; f < FF; f++) {
            float xf = __shfl_sync(0xffffffffu, xv, f);
            a0 += xf * Wt[f][lane];
            a1 += xf * Wt[f][lane + 32];
        }
        int bs = row / NN, n = row - bs * NN;
        size_t base = ((size_t)n * BS_ + bs) * DD;
        g_X[base + lane]      = gelu_f(a0);
        g_X[base + lane + 32] = gelu_f(a1);
    }
}

// =====================================================================
// 2) adjacency: adjT[m][n] = softmax_over_m((from[n].to[m]) * 2)
// =====================================================================
__global__ __launch_bounds__(256) void k_adj(
    const float* __restrict__ fe, const float* __restrict__ te)
{
    __shared__ float fl[32];
    __shared__ float lg[NN];
    __shared__ float redm[8], reds[8];
    int n = blockIdx.x, tid = threadIdx.x;
    int lane = tid & 31, warp = tid >> 5;
    if (tid < 32) fl[tid] = fe[n * 32 + tid];
    __syncthreads();

    float lmax = -1e30f;
    for (int m = tid; m < NN; m += 256) {
        float s = 0.f;
#pragma unroll
        for (int f = 0; f < 32; f++) s += fl[f] * te[m * 32 + f];
        s *= 2.0f;
        lg[m] = s;
        lmax = fmaxf(lmax, s);
    }
#pragma unroll
    for (int o = 16; o; o >>= 1) lmax = fmaxf(lmax, __shfl_xor_sync(0xffffffffu, lmax, o));
    if (lane == 0) redm[warp] = lmax;
    __syncthreads();
    float mx = redm[0];
#pragma unroll
    for (int w = 1; w < 8; w++) mx = fmaxf(mx, redm[w]);

    float lsum = 0.f;
    for (int m = tid; m < NN; m += 256) {
        float e = expf(lg[m] - mx);
        lg[m] = e;
        lsum += e;
    }
#pragma unroll
    for (int o = 16; o; o >>= 1) lsum += __shfl_xor_sync(0xffffffffu, lsum, o);
    if (lane == 0) reds[warp] = lsum;
    __syncthreads();
    float tot = 0.f;
#pragma unroll
    for (int w = 0; w < 8; w++) tot += reds[w];
    float inv = 1.0f / tot;
    for (int m = tid; m < NPAD; m += 256)
        g_adjT[m * NPAD + n] = (m < NN) ? lg[m] * inv : 0.f;
}

// =====================================================================
// 3) aggregation GEMM on tensor cores (tf32 3-split):
//    Y(512x65536) = adjT(512x512) @ X(512x65536)
//    CTA 128x128x16, 8 warps of 64x32; mma.sync m16n8k8
// =====================================================================
#define ASTR 136   // 136 % 32 == 8 -> conflict-free fragment loads
__global__ __launch_bounds__(256) void k_agg_tc()
{
    __shared__ float Ah[16][ASTR], Al[16][ASTR];
    __shared__ float Bh[16][ASTR], Bl[16][ASTR];

    int tid = threadIdx.x;
    int m0 = blockIdx.y * 128, n0 = blockIdx.x * 128;
    int wid = tid >> 5, lane = tid & 31;
    int g = lane >> 2, tig = lane & 3;
    int wm = (wid & 1) * 64, wn = (wid >> 1) * 32;

    int a_r = tid >> 1,  a_kc = (tid & 1) * 4;   // A: row a_r, k = a_kc..a_kc+3 and +8
    int b_k = tid >> 4,  b_c = (tid & 15) * 4;   // B: k row b_k, cols b_c and b_c+64

    float acc[4][4][4];
#pragma unroll
    for (int mt = 0; mt < 4; mt++)
#pragma unroll
        for (int nt = 0; nt < 4; nt++)
#pragma unroll
            for (int r = 0; r < 4; r++) acc[mt][nt][r] = 0.f;

    const float* A  = g_adjT;
    const float* Bm = g_X;

    float4 aR0 = *(const float4*)&A[(m0 + a_r) * NPAD + a_kc];
    float4 aR1 = *(const float4*)&A[(m0 + a_r) * NPAD + a_kc + 8];
    float4 bR0 = *(const float4*)&Bm[(size_t)b_k * GDCOL + n0 + b_c];
    float4 bR1 = *(const float4*)&Bm[(size_t)b_k * GDCOL + n0 + b_c + 64];

    for (int kt = 0; kt < 32; kt++) {
        // split current tile into smem
        {
            float av[8] = {aR0.x, aR0.y, aR0.z, aR0.w, aR1.x, aR1.y, aR1.z, aR1.w};
#pragma unroll
            for (int i = 0; i < 4; i++) {
                float h, l;
                split_tf32(av[i], h, l);
                Ah[a_kc + i][a_r] = h; Al[a_kc + i][a_r] = l;
                split_tf32(av[4 + i], h, l);
                Ah[a_kc + 8 + i][a_r] = h; Al[a_kc + 8 + i][a_r] = l;
            }
            float4 h4, l4;
            split_tf32(bR0.x, h4.x, l4.x); split_tf32(bR0.y, h4.y, l4.y);
            split_tf32(bR0.z, h4.z, l4.z); split_tf32(bR0.w, h4.w, l4.w);
            *(float4*)&Bh[b_k][b_c] = h4; *(float4*)&Bl[b_k][b_c] = l4;
            split_tf32(bR1.x, h4.x, l4.x); split_tf32(bR1.y, h4.y, l4.y);
            split_tf32(bR1.z, h4.z, l4.z); split_tf32(bR1.w, h4.w, l4.w);
            *(float4*)&Bh[b_k][b_c + 64] = h4; *(float4*)&Bl[b_k][b_c + 64] = l4;
        }
        __syncthreads();

        if (kt + 1 < 32) {
            int k0 = (kt + 1) * 16;
            aR0 = *(const float4*)&A[(m0 + a_r) * NPAD + k0 + a_kc];
            aR1 = *(const float4*)&A[(m0 + a_r) * NPAD + k0 + a_kc + 8];
            bR0 = *(const float4*)&Bm[(size_t)(k0 + b_k) * GDCOL + n0 + b_c];
            bR1 = *(const float4*)&Bm[(size_t)(k0 + b_k) * GDCOL + n0 + b_c + 64];
        }

#pragma unroll
        for (int s = 0; s < 2; s++) {
            int kk = s * 8;
            uint32_t ah[4][4], al[4][4];
#pragma unroll
            for (int mt = 0; mt < 4; mt++) {
                int mrow = wm + mt * 16 + g;
                ah[mt][0] = __float_as_uint(Ah[kk + tig][mrow]);
                ah[mt][1] = __float_as_uint(Ah[kk + tig][mrow + 8]);
                ah[mt][2] = __float_as_uint(Ah[kk + tig + 4][mrow]);
                ah[mt][3] = __float_as_uint(Ah[kk + tig + 4][mrow + 8]);
                al[mt][0] = __float_as_uint(Al[kk + tig][mrow]);
                al[mt][1] = __float_as_uint(Al[kk + tig][mrow + 8]);
                al[mt][2] = __float_as_uint(Al[kk + tig + 4][mrow]);
                al[mt][3] = __float_as_uint(Al[kk + tig + 4][mrow + 8]);
            }
            uint32_t bh[4][2], bl[4][2];
#pragma unroll
            for (int nt = 0; nt < 4; nt++) {
                int ncol = wn + nt * 8 + g;
                bh[nt][0] = __float_as_uint(Bh[kk + tig][ncol]);
                bh[nt][1] = __float_as_uint(Bh[kk + tig + 4][ncol]);
                bl[nt][0] = __float_as_uint(Bl[kk + tig][ncol]);
                bl[nt][1] = __float_as_uint(Bl[kk + tig + 4][ncol]);
            }
#pragma unroll
            for (int mt = 0; mt < 4; mt++)
#pragma unroll
                for (int nt = 0; nt < 4; nt++) {
                    mma_tf32(acc[mt][nt], ah[mt], bh[nt]);
                    mma_tf32(acc[mt][nt], ah[mt], bl[nt]);
                    mma_tf32(acc[mt][nt], al[mt], bh[nt]);
                }
        }
        __syncthreads();
    }

#pragma unroll
    for (int mt = 0; mt < 4; mt++) {
#pragma unroll
        for (int nt = 0; nt < 4; nt++) {
            int row = m0 + wm + mt * 16 + g;
            int col = n0 + wn + nt * 8 + tig * 2;
            float2 v0 = make_float2(acc[mt][nt][0], acc[mt][nt][1]);
            float2 v1 = make_float2(acc[mt][nt][2], acc[mt][nt][3]);
            *(float2*)&g_Y[(size_t)row * GDCOL + col]       = v0;
            *(float2*)&g_Y[(size_t)(row + 8) * GDCOL + col] = v1;
        }
    }
}

// =====================================================================
// 4) per-token: h = gelu((X+Y) @ W^T + b); x' = LN(h)*g+be
//    warp per token; lane owns outputs e=2*lane, 2*lane+1.
//    u broadcast from smem (LDS.128), W via conflict-free LDS.64.
// =====================================================================
__global__ __launch_bounds__(256) void k_token(
    const float* __restrict__ W, const float* __restrict__ bvec,
    const float* __restrict__ gvec, const float* __restrict__ bevec, int mode)
{
    __shared__ float Wt2[64 * 64];           // Wt2[d*64 + e] = W[e*64 + d]
    __shared__ float sb[64], sg[64], sbe[64];
    __shared__ float ush[8][64];
    int tid = threadIdx.x;
    for (int q = tid; q < 4096; q += 256) {
        int e = q >> 6, d = q & 63;
        Wt2[d * 64 + e] = W[q];
    }
    if (tid < 64) { sb[tid] = bvec[tid]; sg[tid] = gvec[tid]; sbe[tid] = bevec[tid]; }
    __syncthreads();
    int warp = tid >> 5, lane = tid & 31;
    float2 bb = *(const float2*)&sb[2 * lane];
    float2 gg = *(const float2*)&sg[2 * lane];
    float2 be = *(const float2*)&sbe[2 * lane];

    for (int it = 0; it < 16; it++) {
        int tok = (blockIdx.x * 16 + it) * 8 + warp;   // tok = n*1024 + bs
        size_t base = (size_t)tok * 64;
        float u0 = g_X[base + lane]      + g_Y[base + lane];
        float u1 = g_X[base + lane + 32] + g_Y[base + lane + 32];
        ush[warp][lane]      = u0;
        ush[warp][lane + 32] = u1;
        __syncwarp();

        float a0 = bb.x, a1 = bb.y;
#pragma unroll
        for (int db = 0; db < 16; db++) {
            float4 uv = *(const float4*)&ush[warp][db * 4];
            float2 w0 = *(const float2*)&Wt2[(db * 4 + 0) * 64 + 2 * lane];
            float2 w1 = *(const float2*)&Wt2[(db * 4 + 1) * 64 + 2 * lane];
            float2 w2 = *(const float2*)&Wt2[(db * 4 + 2) * 64 + 2 * lane];
            float2 w3 = *(const float2*)&Wt2[(db * 4 + 3) * 64 + 2 * lane];
            a0 += uv.x * w0.x + uv.y * w1.x + uv.z * w2.x + uv.w * w3.x;
            a1 += uv.x * w0.y + uv.y * w1.y + uv.z * w2.y + uv.w * w3.y;
        }
        __syncwarp();

        float h0 = gelu_f(a0), h1 = gelu_f(a1);
        float s = h0 + h1;
#pragma unroll
        for (int o = 16; o; o >>= 1) s += __shfl_xor_sync(0xffffffffu, s, o);
        float mu = s * (1.0f / 64.0f);
        float d0 = h0 - mu, d1 = h1 - mu;
        float v = d0 * d0 + d1 * d1;
#pragma unroll
        for (int o = 16; o; o >>= 1) v += __shfl_xor_sync(0xffffffffu, v, o);
        float inv = rsqrtf(v * (1.0f / 64.0f) + 1e-5f);
        float o0 = d0 * inv * gg.x + be.x;
        float o1 = d1 * inv * gg.y + be.y;
        if (mode == 0) {
            *(float2*)&g_X[base + 2 * lane] = make_float2(o0, o1);
        } else {
            int m = tok >> 10, bs = tok & 1023;
            size_t ob = (size_t)bs * KIN + (size_t)m * 64;
            *(float2*)&g_flat[ob + 2 * lane] = make_float2(o0, o1);
        }
    }
}

// =====================================================================
// 5) GRU input projection (split-K FFMA GEMM) — unchanged
// =====================================================================
__global__ __launch_bounds__(256) void k_xp(
    const float* __restrict__ W, int T, int Mtot, int KCH, int sel)
{
    __shared__ float As[2][8][65];
    __shared__ float Bs[2][8][65];
    float* part = (sel == 0) ? g_part_l : (sel == 1) ? g_part_m : g_part_s;

    int tid = threadIdx.x;
    int m0 = blockIdx.x * 64;
    int n0 = blockIdx.y * 64;
    int z  = blockIdx.z;
    int kbase = z * KCH;

    int a_r = tid >> 2;
    int a_k = (tid & 3) * 2;
    int b_g = tid >> 2;
    int b_k = (tid & 3) * 2;
    int ty = tid >> 4, tx = tid & 15;

    int r = m0 + a_r;
    bool a_valid = (r < Mtot);
    const float* aptr = g_flat;
    if (a_valid) {
        int bb = r / T, tt = r - bb * T;
        int frow = bb * S_ + (S_ - T) + tt;
        aptr = g_flat + (size_t)frow * KIN;
    }
    const float* bptr = W + (size_t)(n0 + b_g) * KIN;

    float acc[4][4];
#pragma unroll
    for (int i = 0; i < 4; i++)
#pragma unroll
        for (int j = 0; j < 4; j++) acc[i][j] = 0.f;

    int NT = KCH / 8;
    float2 aReg = a_valid ? *(const float2*)(aptr + kbase + a_k) : make_float2(0.f, 0.f);
    float2 bReg = *(const float2*)(bptr + kbase + b_k);
    As[0][a_k][a_r] = aReg.x; As[0][a_k + 1][a_r] = aReg.y;
    Bs[0][b_k][b_g] = bReg.x; Bs[0][b_k + 1][b_g] = bReg.y;
    __syncthreads();

    for (int kt = 0; kt < NT; kt++) {
        int cur = kt & 1, nxt = cur ^ 1;
        if (kt + 1 < NT) {
            int k0 = kbase + (kt + 1) * 8;
            aReg = a_valid ? *(const float2*)(aptr + k0 + a_k) : make_float2(0.f, 0.f);
            bReg = *(const float2*)(bptr + k0 + b_k);
        }
#pragma unroll
        for (int k = 0; k < 8; k++) {
            float af[4], bf[4];
#pragma unroll
            for (int i = 0; i < 4; i++) af[i] = As[cur][k][ty * 4 + i];
#pragma unroll
            for (int j = 0; j < 4; j++) bf[j] = Bs[cur][k][tx * 4 + j];
#pragma unroll
            for (int i = 0; i < 4; i++)
#pragma unroll
                for (int j = 0; j < 4; j++)
                    acc[i][j] += af[i] * bf[j];
        }
        if (kt + 1 < NT) {
            As[nxt][a_k][a_r] = aReg.x; As[nxt][a_k + 1][a_r] = aReg.y;
            Bs[nxt][b_k][b_g] = bReg.x; Bs[nxt][b_k + 1][b_g] = bReg.y;
        }
        __syncthreads();
    }

#pragma unroll
    for (int i = 0; i < 4; i++) {
        int rr = m0 + ty * 4 + i;
        if (rr < Mtot) {
#pragma unroll
            for (int j = 0; j < 4; j++) {
                int gg = n0 + tx * 4 + j;
                part[((size_t)z * Mtot + rr) * I3D + gg] = acc[i][j];
            }
        }
    }
}

__global__ void k_xp_reduce(const float* __restrict__ bih, int Mtot, int sel)
{
    const float* part = (sel == 0) ? g_part_l : (sel == 1) ? g_part_m : g_part_s;
    float* out = (sel == 0) ? g_xp_l : (sel == 1) ? g_xp_m : g_xp_s;
    int i = blockIdx.x * 256 + threadIdx.x;
    int tot = Mtot * I3D;
    if (i >= tot) return;
    int g = i % I3D;
    float s = bih[g];
    for (int z = 0; z < SPLITK; z++) s += part[(size_t)z * tot + i];
    out[i] = s;
}

// =====================================================================
// 6) GRU recurrence — unchanged
// =====================================================================
__global__ __launch_bounds__(192) void k_gru(
    const float* __restrict__ Whh_s, const float* __restrict__ bhh_s,
    const float* __restrict__ Whh_m, const float* __restrict__ bhh_m,
    const float* __restrict__ Whh_l, const float* __restrict__ bhh_l)
{
    int blk = blockIdx.x;
    int gru = blk >> 2;
    int b = blk & 3;
    int T = (gru == 0) ? 10 : (gru == 1) ? 20 : 256;
    const float* xp  = (gru == 0) ? g_xp_s : (gru == 1) ? g_xp_m : g_xp_l;
    const float* Whh = (gru == 0) ? Whh_s : (gru == 1) ? Whh_m : Whh_l;
    const float* bhh = (gru == 0) ? bhh_s : (gru == 1) ? bhh_m : bhh_l;
    int g = threadIdx.x;

    float w[64];
#pragma unroll
    for (int d = 0; d < 64; d += 4) {
        float4 v = *(const float4*)&Whh[g * 64 + d];
        w[d] = v.x; w[d + 1] = v.y; w[d + 2] = v.z; w[d + 3] = v.w;
    }
    float bh = bhh[g];

    __shared__ float h_sh[64], r_sh[64], z_sh[64], n_sh[64];
    if (g < 64) h_sh[g] = 0.f;
    __syncthreads();

    const float* xpb = xp + (size_t)b * T * I3D;
    for (int t = 0; t < T; t++) {
        float a0 = 0.f, a1 = 0.f, a2 = 0.f, a3 = 0.f;
#pragma unroll
        for (int d = 0; d < 64; d += 4) {
            a0 += w[d]     * h_sh[d];
            a1 += w[d + 1] * h_sh[d + 1];
            a2 += w[d + 2] * h_sh[d + 2];
            a3 += w[d + 3] * h_sh[d + 3];
        }
        float gh = bh + ((a0 + a1) + (a2 + a3));
        float xv = xpb[t * I3D + g];
        if (g < 64) {
            r_sh[g] = sigm_f(xv + gh);
        } else if (g < 128) {
            z_sh[g - 64] = sigm_f(xv + gh);
        }
        __syncthreads();
        if (g >= 128) {
            n_sh[g - 128] = tanhf(xv + r_sh[g - 128] * gh);
        }
        __syncthreads();
        if (g < 64) {
            float zz = z_sh[g], nn = n_sh[g];
            h_sh[g] = (1.f - zz) * nn + zz * h_sh[g];
        }
        __syncthreads();
    }
    if (g < 64) g_hcat[b * I3D + gru * 64 + g] = h_sh[g];
}

// =====================================================================
// 7) head — unchanged
// =====================================================================
__global__ __launch_bounds__(256) void k_head(
    const float* __restrict__ W1, const float* __restrict__ b1,
    const float* __restrict__ W2, const float* __restrict__ b2,
    float* __restrict__ out)
{
    __shared__ float hc[4 * I3D];
    __shared__ float h1[4 * 64];
    int t = threadIdx.x;
    for (int i = t; i < 4 * I3D; i += 256) hc[i] = g_hcat[i];
    __syncthreads();
    {
        int b = t >> 6, e = t & 63;
        float a = b1[e];
#pragma unroll 8
        for (int gg = 0; gg < I3D; gg++) a += hc[b * I3D + gg] * W1[e * I3D + gg];
        h1[b * 64 + e] = gelu_f(a);
    }
    __syncthreads();
    for (int q = t; q < 4 * NN; q += 256) {
        int b = q / NN, n = q - b * NN;
        float a = b2[n];
#pragma unroll 8
        for (int e = 0; e < 64; e++) a += h1[b * 64 + e] * W2[n * 64 + e];
        out[b * NN + n] = a;
    }
}

// =====================================================================
// launcher
// =====================================================================
extern "C" void kernel_launch(void* const* d_in, const int* in_sizes, int n_in,
                              void* d_out, int out_size)
{
    const float* x     = (const float*)d_in[0];
    const float* ipW   = (const float*)d_in[1];
    const float* ipb   = (const float*)d_in[2];
    const float* fe    = (const float*)d_in[3];
    const float* te    = (const float*)d_in[4];
    const float* glW   = (const float*)d_in[5];
    const float* glb   = (const float*)d_in[6];
    const float* glg   = (const float*)d_in[7];
    const float* glbe  = (const float*)d_in[8];
    const float* Wih_s = (const float*)d_in[9];
    const float* Whh_s = (const float*)d_in[10];
    const float* bih_s = (const float*)d_in[11];
    const float* bhh_s = (const float*)d_in[12];
    const float* Wih_m = (const float*)d_in[13];
    const float* Whh_m = (const float*)d_in[14];
    const float* bih_m = (const float*)d_in[15];
    const float* bhh_m = (const float*)d_in[16];
    const float* Wih_l = (const float*)d_in[17];
    const float* Whh_l = (const float*)d_in[18];
    const float* bih_l = (const float*)d_in[19];
    const float* bhh_l = (const float*)d_in[20];
    const float* dhW1  = (const float*)d_in[21];
    const float* dhb1  = (const float*)d_in[22];
    const float* dhW2  = (const float*)d_in[23];
    const float* dhb2  = (const float*)d_in[24];
    float* out = (float*)d_out;

    k_input_proj<<<4000, 256>>>(x, ipW, ipb);
    k_adj<<<NN, 256>>>(fe, te);

    // layer 0
    k_agg_tc<<<dim3(GDCOL / 128, 4), 256>>>();
    k_token<<<4000, 256>>>(glW, glb, glg, glbe, 0);
    // layer 1
    k_agg_tc<<<dim3(GDCOL / 128, 4), 256>>>();
    k_token<<<4000, 256>>>(glW + 4096, glb + 64, glg + 64, glbe + 64, 1);

    // GRU input projections (split-K)
    k_xp<<<dim3(16, 3, SPLITK), 256>>>(Wih_l, 256, 1024, KCH_L, 0);
    k_xp<<<dim3(2, 3, SPLITK), 256>>>(Wih_m, 20, 80, KCH_L, 1);
    k_xp<<<dim3(1, 3, SPLITK), 256>>>(Wih_s, 10, 40, KCH_L, 2);
    k_xp_reduce<<<(1024 * I3D + 255) / 256, 256>>>(bih_l, 1024, 0);
    k_xp_reduce<<<(80 * I3D + 255) / 256, 256>>>(bih_m, 80, 1);
    k_xp_reduce<<<(40 * I3D + 255) / 256, 256>>>(bih_s, 40, 2);

    k_gru<<<12, 192>>>(Whh_s, bhh_s, Whh_m, bhh_m, Whh_l, bhh_l);
    k_head<<<1, 256>>>(dhW1, dhb1, dhW2, dhb2, out);
}

// round 7
// speedup vs baseline: 1.1919x; 1.0847x over previous
#include <cuda_runtime.h>
#include <math.h>
#include <stdint.h>

// ---------------- problem constants ----------------
#define B_    4
#define S_    256
#define BS_   1024          // B*S
#define NN    500           // nodes
#define NPAD  512
#define FF    32
#define DD    64
#define GDCOL 65536         // BS_*DD
#define I3D   192
#define KIN   32000
#define SPLITK 25
#define KCH_L  1280         // 32000/25

// ---------------- device scratch (static zero-init; pads never written) ----------------
__device__ __align__(16) float g_X[(size_t)NPAD * BS_ * DD];
__device__ __align__(16) float g_Y[(size_t)NPAD * BS_ * DD];
__device__ __align__(16) float g_flat[(size_t)BS_ * KIN];
__device__ __align__(16) float g_adjT[NPAD * NPAD];
__device__ __align__(16) float g_part_l[SPLITK * BS_ * I3D];
__device__ __align__(16) float g_part_m[SPLITK * 80 * I3D];
__device__ __align__(16) float g_part_s[SPLITK * 40 * I3D];
__device__ __align__(16) float g_xp_l[BS_ * I3D];
__device__ __align__(16) float g_xp_m[80 * I3D];
__device__ __align__(16) float g_xp_s[40 * I3D];
__device__ __align__(16) float g_hcat[4 * I3D];

__device__ __forceinline__ float gelu_f(float x) {
    return 0.5f * x * (1.0f + erff(x * 0.7071067811865476f));
}
__device__ __forceinline__ float sigm_f(float x) {
    return 1.0f / (1.0f + expf(-x));
}

// tf32 split helpers
__device__ __forceinline__ uint32_t to_tf32(float v) {
    uint32_t r;
    asm("cvt.rna.tf32.f32 %0, %1;" : "=r"(r) : "f"(v));
    return r;
}
__device__ __forceinline__ void split_tf32(float v, float& hi, float& lo) {
    uint32_t h = to_tf32(v);
    hi = __uint_as_float(h);
    lo = __uint_as_float(to_tf32(v - hi));
}
__device__ __forceinline__ void mma_tf32(float* c, const uint32_t* a, const uint32_t* b) {
    asm volatile(
        "mma.sync.aligned.m16n8k8.row.col.f32.tf32.tf32.f32 "
        "{%0,%1,%2,%3}, {%4,%5,%6,%7}, {%8,%9}, {%0,%1,%2,%3};"
        : "+f"(c[0]), "+f"(c[1]), "+f"(c[2]), "+f"(c[3])
        : "r"(a[0]), "r"(a[1]), "r"(a[2]), "r"(a[3]), "r"(b[0]), "r"(b[1]));
}

// =====================================================================
// 1) input projection: X[n][bs][d] = gelu(sum_f x[bs][n][f]*ipW[d][f] + b[d])
// =====================================================================
__global__ __launch_bounds__(256) void k_input_proj(
    const float* __restrict__ x, const float* __restrict__ ipW, const float* __restrict__ ipb)
{
    __shared__ float Wt[FF][DD];   // Wt[f][d]
    __shared__ float sb[DD];
    int tid = threadIdx.x;
    for (int q = tid; q < FF * DD; q += 256) {
        int d = q >> 5, f = q & 31;          // ipW row-major [d][f]
        Wt[f][d] = ipW[q];
    }
    if (tid < DD) sb[tid] = ipb[tid];
    __syncthreads();
    int warp = tid >> 5, lane = tid & 31;
    for (int it = 0; it < 16; it++) {
        int row = (blockIdx.x * 16 + it) * 8 + warp;   // row = bs*500+n, < 512000
        float xv = x[(size_t)row * FF + lane];
        float a0 = sb[lane], a1 = sb[lane + 32];
#pragma unroll
        for (int f = 0; f < FF; f++) {
            float xf = __shfl_sync(0xffffffffu, xv, f);
            a0 += xf * Wt[f][lane];
            a1 += xf * Wt[f][lane + 32];
        }
        int bs = row / NN, n = row - bs * NN;
        size_t base = ((size_t)n * BS_ + bs) * DD;
        g_X[base + lane]      = gelu_f(a0);
        g_X[base + lane + 32] = gelu_f(a1);
    }
}

// =====================================================================
// 2) adjacency: adjT[m][n] = softmax_over_m((from[n].to[m]) * 2)
// =====================================================================
__global__ __launch_bounds__(256) void k_adj(
    const float* __restrict__ fe, const float* __restrict__ te)
{
    __shared__ float fl[32];
    __shared__ float lg[NN];
    __shared__ float redm[8], reds[8];
    int n = blockIdx.x, tid = threadIdx.x;
    int lane = tid & 31, warp = tid >> 5;
    if (tid < 32) fl[tid] = fe[n * 32 + tid];
    __syncthreads();

    float lmax = -1e30f;
    for (int m = tid; m < NN; m += 256) {
        float s = 0.f;
#pragma unroll
        for (int f = 0; f < 32; f++) s += fl[f] * te[m * 32 + f];
        s *= 2.0f;
        lg[m] = s;
        lmax = fmaxf(lmax, s);
    }
#pragma unroll
    for (int o = 16; o; o >>= 1) lmax = fmaxf(lmax, __shfl_xor_sync(0xffffffffu, lmax, o));
    if (lane == 0) redm[warp] = lmax;
    __syncthreads();
    float mx = redm[0];
#pragma unroll
    for (int w = 1; w < 8; w++) mx = fmaxf(mx, redm[w]);

    float lsum = 0.f;
    for (int m = tid; m < NN; m += 256) {
        float e = expf(lg[m] - mx);
        lg[m] = e;
        lsum += e;
    }
#pragma unroll
    for (int o = 16; o; o >>= 1) lsum += __shfl_xor_sync(0xffffffffu, lsum, o);
    if (lane == 0) reds[warp] = lsum;
    __syncthreads();
    float tot = 0.f;
#pragma unroll
    for (int w = 0; w < 8; w++) tot += reds[w];
    float inv = 1.0f / tot;
    for (int m = tid; m < NPAD; m += 256)
        g_adjT[m * NPAD + n] = (m < NN) ? lg[m] * inv : 0.f;
}

// =====================================================================
// 3) aggregation GEMM on tensor cores (tf32 3-split):
//    u = adjT(512x512) @ X(512x65536) + X     (epilogue add)
//    CTA 128x128x16. GRID: m-tile FASTEST -> 4 B-sharing CTAs co-resident.
// =====================================================================
#define ASTR 136   // 136 % 32 == 8 -> conflict-free fragment loads
__global__ __launch_bounds__(256) void k_agg_tc()
{
    __shared__ float Ah[16][ASTR], Al[16][ASTR];
    __shared__ float Bh[16][ASTR], Bl[16][ASTR];

    int tid = threadIdx.x;
    int m0 = blockIdx.x * 128, n0 = blockIdx.y * 128;   // x = m (fastest)
    int wid = tid >> 5, lane = tid & 31;
    int g = lane >> 2, tig = lane & 3;
    int wm = (wid & 1) * 64, wn = (wid >> 1) * 32;

    int a_r = tid >> 1,  a_kc = (tid & 1) * 4;
    int b_k = tid >> 4,  b_c = (tid & 15) * 4;

    float acc[4][4][4];
#pragma unroll
    for (int mt = 0; mt < 4; mt++)
#pragma unroll
        for (int nt = 0; nt < 4; nt++)
#pragma unroll
            for (int r = 0; r < 4; r++) acc[mt][nt][r] = 0.f;

    const float* A  = g_adjT;
    const float* Bm = g_X;

    float4 aR0 = *(const float4*)&A[(m0 + a_r) * NPAD + a_kc];
    float4 aR1 = *(const float4*)&A[(m0 + a_r) * NPAD + a_kc + 8];
    float4 bR0 = *(const float4*)&Bm[(size_t)b_k * GDCOL + n0 + b_c];
    float4 bR1 = *(const float4*)&Bm[(size_t)b_k * GDCOL + n0 + b_c + 64];

    for (int kt = 0; kt < 32; kt++) {
        {
            float av[8] = {aR0.x, aR0.y, aR0.z, aR0.w, aR1.x, aR1.y, aR1.z, aR1.w};
#pragma unroll
            for (int i = 0; i < 4; i++) {
                float h, l;
                split_tf32(av[i], h, l);
                Ah[a_kc + i][a_r] = h; Al[a_kc + i][a_r] = l;
                split_tf32(av[4 + i], h, l);
                Ah[a_kc + 8 + i][a_r] = h; Al[a_kc + 8 + i][a_r] = l;
            }
            float4 h4, l4;
            split_tf32(bR0.x, h4.x, l4.x); split_tf32(bR0.y, h4.y, l4.y);
            split_tf32(bR0.z, h4.z, l4.z); split_tf32(bR0.w, h4.w, l4.w);
            *(float4*)&Bh[b_k][b_c] = h4; *(float4*)&Bl[b_k][b_c] = l4;
            split_tf32(bR1.x, h4.x, l4.x); split_tf32(bR1.y, h4.y, l4.y);
            split_tf32(bR1.z, h4.z, l4.z); split_tf32(bR1.w, h4.w, l4.w);
            *(float4*)&Bh[b_k][b_c + 64] = h4; *(float4*)&Bl[b_k][b_c + 64] = l4;
        }
        __syncthreads();

        if (kt + 1 < 32) {
            int k0 = (kt + 1) * 16;
            aR0 = *(const float4*)&A[(m0 + a_r) * NPAD + k0 + a_kc];
            aR1 = *(const float4*)&A[(m0 + a_r) * NPAD + k0 + a_kc + 8];
            bR0 = *(const float4*)&Bm[(size_t)(k0 + b_k) * GDCOL + n0 + b_c];
            bR1 = *(const float4*)&Bm[(size_t)(k0 + b_k) * GDCOL + n0 + b_c + 64];
        }

#pragma unroll
        for (int s = 0; s < 2; s++) {
            int kk = s * 8;
            uint32_t ah[4][4], al[4][4];
#pragma unroll
            for (int mt = 0; mt < 4; mt++) {
                int mrow = wm + mt * 16 + g;
                ah[mt][0] = __float_as_uint(Ah[kk + tig][mrow]);
                ah[mt][1] = __float_as_uint(Ah[kk + tig][mrow + 8]);
                ah[mt][2] = __float_as_uint(Ah[kk + tig + 4][mrow]);
                ah[mt][3] = __float_as_uint(Ah[kk + tig + 4][mrow + 8]);
                al[mt][0] = __float_as_uint(Al[kk + tig][mrow]);
                al[mt][1] = __float_as_uint(Al[kk + tig][mrow + 8]);
                al[mt][2] = __float_as_uint(Al[kk + tig + 4][mrow]);
                al[mt][3] = __float_as_uint(Al[kk + tig + 4][mrow + 8]);
            }
            uint32_t bh[4][2], bl[4][2];
#pragma unroll
            for (int nt = 0; nt < 4; nt++) {
                int ncol = wn + nt * 8 + g;
                bh[nt][0] = __float_as_uint(Bh[kk + tig][ncol]);
                bh[nt][1] = __float_as_uint(Bh[kk + tig + 4][ncol]);
                bl[nt][0] = __float_as_uint(Bl[kk + tig][ncol]);
                bl[nt][1] = __float_as_uint(Bl[kk + tig + 4][ncol]);
            }
#pragma unroll
            for (int mt = 0; mt < 4; mt++)
#pragma unroll
                for (int nt = 0; nt < 4; nt++) {
                    mma_tf32(acc[mt][nt], ah[mt], bh[nt]);
                    mma_tf32(acc[mt][nt], ah[mt], bl[nt]);
                    mma_tf32(acc[mt][nt], al[mt], bh[nt]);
                }
        }
        __syncthreads();
    }

    // epilogue: u = agg + X (X tile is L2-warm: it was streamed as B this block)
#pragma unroll
    for (int mt = 0; mt < 4; mt++) {
#pragma unroll
        for (int nt = 0; nt < 4; nt++) {
            int row = m0 + wm + mt * 16 + g;
            int col = n0 + wn + nt * 8 + tig * 2;
            size_t i0 = (size_t)row * GDCOL + col;
            size_t i1 = (size_t)(row + 8) * GDCOL + col;
            float2 x0 = *(const float2*)&g_X[i0];
            float2 x1 = *(const float2*)&g_X[i1];
            *(float2*)&g_Y[i0] = make_float2(acc[mt][nt][0] + x0.x, acc[mt][nt][1] + x0.y);
            *(float2*)&g_Y[i1] = make_float2(acc[mt][nt][2] + x1.x, acc[mt][nt][3] + x1.y);
        }
    }
}

// =====================================================================
// 4) token transform on tensor cores: h = gelu(u @ W^T + b); out = LN(h)*g+be
//    tokens on M (u rows contiguous 64 floats). 128 tokens/block, warp=16.
// =====================================================================
__global__ __launch_bounds__(256) void k_token_tc(
    const float* __restrict__ W, const float* __restrict__ bvec,
    const float* __restrict__ gvec, const float* __restrict__ bevec, int mode)
{
    __shared__ float WH[64 * 65], WL[64 * 65];   // [d][e] transposed, split
    __shared__ float sb[64], sg[64], sbe[64];
    int tid = threadIdx.x;
    for (int q = tid; q < 4096; q += 256) {
        int e = q >> 6, d = q & 63;
        float h, l;
        split_tf32(W[q], h, l);                   // W row-major [e][d]
        WH[d * 65 + e] = h; WL[d * 65 + e] = l;
    }
    if (tid < 64) { sb[tid] = bvec[tid]; sg[tid] = gvec[tid]; sbe[tid] = bevec[tid]; }
    __syncthreads();

    int warp = tid >> 5, lane = tid & 31;
    int g8 = lane >> 2, tig = lane & 3;
    int tok0 = blockIdx.x * 128 + warp * 16;
    const float* U = g_Y + (size_t)tok0 * 64;

    // prefetch all raw A fragments (rows g8, g8+8; k = kk*8 + tig / tig+4)
    float araw[8][4];
#pragma unroll
    for (int kk = 0; kk < 8; kk++) {
        araw[kk][0] = U[(size_t)g8 * 64       + kk * 8 + tig];
        araw[kk][1] = U[(size_t)(g8 + 8) * 64 + kk * 8 + tig];
        araw[kk][2] = U[(size_t)g8 * 64       + kk * 8 + tig + 4];
        araw[kk][3] = U[(size_t)(g8 + 8) * 64 + kk * 8 + tig + 4];
    }

    float acc[8][4];
#pragma unroll
    for (int nt = 0; nt < 8; nt++)
#pragma unroll
        for (int r = 0; r < 4; r++) acc[nt][r] = 0.f;

#pragma unroll
    for (int kk = 0; kk < 8; kk++) {
        uint32_t ah[4], al[4];
#pragma unroll
        for (int r = 0; r < 4; r++) {
            float h, l;
            split_tf32(araw[kk][r], h, l);
            ah[r] = __float_as_uint(h); al[r] = __float_as_uint(l);
        }
        int k0 = (kk * 8 + tig) * 65, k1 = (kk * 8 + tig + 4) * 65;
#pragma unroll
        for (int nt = 0; nt < 8; nt++) {
            int e = nt * 8 + g8;
            uint32_t bh[2], bl[2];
            bh[0] = __float_as_uint(WH[k0 + e]);
            bh[1] = __float_as_uint(WH[k1 + e]);
            bl[0] = __float_as_uint(WL[k0 + e]);
            bl[1] = __float_as_uint(WL[k1 + e]);
            mma_tf32(acc[nt], ah, bh);
            mma_tf32(acc[nt], ah, bl);
            mma_tf32(acc[nt], al, bh);
        }
    }

    // bias + gelu
#pragma unroll
    for (int nt = 0; nt < 8; nt++) {
        float2 bb = *(const float2*)&sb[nt * 8 + 2 * tig];
        acc[nt][0] = gelu_f(acc[nt][0] + bb.x);
        acc[nt][1] = gelu_f(acc[nt][1] + bb.y);
        acc[nt][2] = gelu_f(acc[nt][2] + bb.x);
        acc[nt][3] = gelu_f(acc[nt][3] + bb.y);
    }

    // LN over e for rows r0 = tok0+g8, r1 = tok0+g8+8 (reduce across 4-lane quad)
    float s0 = 0.f, s1 = 0.f;
#pragma unroll
    for (int nt = 0; nt < 8; nt++) { s0 += acc[nt][0] + acc[nt][1]; s1 += acc[nt][2] + acc[nt][3]; }
    s0 += __shfl_xor_sync(0xffffffffu, s0, 1); s0 += __shfl_xor_sync(0xffffffffu, s0, 2);
    s1 += __shfl_xor_sync(0xffffffffu, s1, 1); s1 += __shfl_xor_sync(0xffffffffu, s1, 2);
    float mu0 = s0 * (1.0f / 64.0f), mu1 = s1 * (1.0f / 64.0f);
    float v0 = 0.f, v1 = 0.f;
#pragma unroll
    for (int nt = 0; nt < 8; nt++) {
        float d0 = acc[nt][0] - mu0, d1 = acc[nt][1] - mu0;
        float d2 = acc[nt][2] - mu1, d3 = acc[nt][3] - mu1;
        v0 += d0 * d0 + d1 * d1; v1 += d2 * d2 + d3 * d3;
    }
    v0 += __shfl_xor_sync(0xffffffffu, v0, 1); v0 += __shfl_xor_sync(0xffffffffu, v0, 2);
    v1 += __shfl_xor_sync(0xffffffffu, v1, 1); v1 += __shfl_xor_sync(0xffffffffu, v1, 2);
    float inv0 = rsqrtf(v0 * (1.0f / 64.0f) + 1e-5f);
    float inv1 = rsqrtf(v1 * (1.0f / 64.0f) + 1e-5f);

    int r0 = tok0 + g8, r1 = tok0 + g8 + 8;
    float* p0; float* p1;
    if (mode == 0) {
        p0 = g_X + (size_t)r0 * 64;
        p1 = g_X + (size_t)r1 * 64;
    } else {
        p0 = g_flat + (size_t)(r0 & 1023) * KIN + (size_t)(r0 >> 10) * 64;
        p1 = g_flat + (size_t)(r1 & 1023) * KIN + (size_t)(r1 >> 10) * 64;
    }
#pragma unroll
    for (int nt = 0; nt < 8; nt++) {
        int c = nt * 8 + 2 * tig;
        float2 gg = *(const float2*)&sg[c];
        float2 be = *(const float2*)&sbe[c];
        *(float2*)&p0[c] = make_float2((acc[nt][0] - mu0) * inv0 * gg.x + be.x,
                                       (acc[nt][1] - mu0) * inv0 * gg.y + be.y);
        *(float2*)&p1[c] = make_float2((acc[nt][2] - mu1) * inv1 * gg.x + be.x,
                                       (acc[nt][3] - mu1) * inv1 * gg.y + be.y);
    }
}

// =====================================================================
// 5) GRU input projection (split-K FFMA GEMM) — unchanged
// =====================================================================
__global__ __launch_bounds__(256) void k_xp(
    const float* __restrict__ W, int T, int Mtot, int KCH, int sel)
{
    __shared__ float As[2][8][65];
    __shared__ float Bs[2][8][65];
    float* part = (sel == 0) ? g_part_l : (sel == 1) ? g_part_m : g_part_s;

    int tid = threadIdx.x;
    int m0 = blockIdx.x * 64;
    int n0 = blockIdx.y * 64;
    int z  = blockIdx.z;
    int kbase = z * KCH;

    int a_r = tid >> 2;
    int a_k = (tid & 3) * 2;
    int b_g = tid >> 2;
    int b_k = (tid & 3) * 2;
    int ty = tid >> 4, tx = tid & 15;

    int r = m0 + a_r;
    bool a_valid = (r < Mtot);
    const float* aptr = g_flat;
    if (a_valid) {
        int bb = r / T, tt = r - bb * T;
        int frow = bb * S_ + (S_ - T) + tt;
        aptr = g_flat + (size_t)frow * KIN;
    }
    const float* bptr = W + (size_t)(n0 + b_g) * KIN;

    float acc[4][4];
#pragma unroll
    for (int i = 0; i < 4; i++)
#pragma unroll
        for (int j = 0; j < 4; j++) acc[i][j] = 0.f;

    int NT = KCH / 8;
    float2 aReg = a_valid ? *(const float2*)(aptr + kbase + a_k) : make_float2(0.f, 0.f);
    float2 bReg = *(const float2*)(bptr + kbase + b_k);
    As[0][a_k][a_r] = aReg.x; As[0][a_k + 1][a_r] = aReg.y;
    Bs[0][b_k][b_g] = bReg.x; Bs[0][b_k + 1][b_g] = bReg.y;
    __syncthreads();

    for (int kt = 0; kt < NT; kt++) {
        int cur = kt & 1, nxt = cur ^ 1;
        if (kt + 1 < NT) {
            int k0 = kbase + (kt + 1) * 8;
            aReg = a_valid ? *(const float2*)(aptr + k0 + a_k) : make_float2(0.f, 0.f);
            bReg = *(const float2*)(bptr + k0 + b_k);
        }
#pragma unroll
        for (int k = 0; k < 8; k++) {
            float af[4], bf[4];
#pragma unroll
            for (int i = 0; i < 4; i++) af[i] = As[cur][k][ty * 4 + i];
#pragma unroll
            for (int j = 0; j < 4; j++) bf[j] = Bs[cur][k][tx * 4 + j];
#pragma unroll
            for (int i = 0; i < 4; i++)
#pragma unroll
                for (int j = 0; j < 4; j++)
                    acc[i][j] += af[i] * bf[j];
        }
        if (kt + 1 < NT) {
            As[nxt][a_k][a_r] = aReg.x; As[nxt][a_k + 1][a_r] = aReg.y;
            Bs[nxt][b_k][b_g] = bReg.x; Bs[nxt][b_k + 1][b_g] = bReg.y;
        }
        __syncthreads();
    }

#pragma unroll
    for (int i = 0; i < 4; i++) {
        int rr = m0 + ty * 4 + i;
        if (rr < Mtot) {
#pragma unroll
            for (int j = 0; j < 4; j++) {
                int gg = n0 + tx * 4 + j;
                part[((size_t)z * Mtot + rr) * I3D + gg] = acc[i][j];
            }
        }
    }
}

__global__ void k_xp_reduce(const float* __restrict__ bih, int Mtot, int sel)
{
    const float* part = (sel == 0) ? g_part_l : (sel == 1) ? g_part_m : g_part_s;
    float* out = (sel == 0) ? g_xp_l : (sel == 1) ? g_xp_m : g_xp_s;
    int i = blockIdx.x * 256 + threadIdx.x;
    int tot = Mtot * I3D;
    if (i >= tot) return;
    int g = i % I3D;
    float s = bih[g];
    for (int z = 0; z < SPLITK; z++) s += part[(size_t)z * tot + i];
    out[i] = s;
}

// =====================================================================
// 6) GRU recurrence — unchanged
// =====================================================================
__global__ __launch_bounds__(192) void k_gru(
    const float* __restrict__ Whh_s, const float* __restrict__ bhh_s,
    const float* __restrict__ Whh_m, const float* __restrict__ bhh_m,
    const float* __restrict__ Whh_l, const float* __restrict__ bhh_l)
{
    int blk = blockIdx.x;
    int gru = blk >> 2;
    int b = blk & 3;
    int T = (gru == 0) ? 10 : (gru == 1) ? 20 : 256;
    const float* xp  = (gru == 0) ? g_xp_s : (gru == 1) ? g_xp_m : g_xp_l;
    const float* Whh = (gru == 0) ? Whh_s : (gru == 1) ? Whh_m : Whh_l;
    const float* bhh = (gru == 0) ? bhh_s : (gru == 1) ? bhh_m : bhh_l;
    int g = threadIdx.x;

    float w[64];
#pragma unroll
    for (int d = 0; d < 64; d += 4) {
        float4 v = *(const float4*)&Whh[g * 64 + d];
        w[d] = v.x; w[d + 1] = v.y; w[d + 2] = v.z; w[d + 3] = v.w;
    }
    float bh = bhh[g];

    __shared__ float h_sh[64], r_sh[64], z_sh[64], n_sh[64];
    if (g < 64) h_sh[g] = 0.f;
    __syncthreads();

    const float* xpb = xp + (size_t)b * T * I3D;
    for (int t = 0; t < T; t++) {
        float a0 = 0.f, a1 = 0.f, a2 = 0.f, a3 = 0.f;
#pragma unroll
        for (int d = 0; d < 64; d += 4) {
            a0 += w[d]     * h_sh[d];
            a1 += w[d + 1] * h_sh[d + 1];
            a2 += w[d + 2] * h_sh[d + 2];
            a3 += w[d + 3] * h_sh[d + 3];
        }
        float gh = bh + ((a0 + a1) + (a2 + a3));
        float xv = xpb[t * I3D + g];
        if (g < 64) {
            r_sh[g] = sigm_f(xv + gh);
        } else if (g < 128) {
            z_sh[g - 64] = sigm_f(xv + gh);
        }
        __syncthreads();
        if (g >= 128) {
            n_sh[g - 128] = tanhf(xv + r_sh[g - 128] * gh);
        }
        __syncthreads();
        if (g < 64) {
            float zz = z_sh[g], nn = n_sh[g];
            h_sh[g] = (1.f - zz) * nn + zz * h_sh[g];
        }
        __syncthreads();
    }
    if (g < 64) g_hcat[b * I3D + gru * 64 + g] = h_sh[g];
}

// =====================================================================
// 7) head — unchanged
// =====================================================================
__global__ __launch_bounds__(256) void k_head(
    const float* __restrict__ W1, const float* __restrict__ b1,
    const float* __restrict__ W2, const float* __restrict__ b2,
    float* __restrict__ out)
{
    __shared__ float hc[4 * I3D];
    __shared__ float h1[4 * 64];
    int t = threadIdx.x;
    for (int i = t; i < 4 * I3D; i += 256) hc[i] = g_hcat[i];
    __syncthreads();
    {
        int b = t >> 6, e = t & 63;
        float a = b1[e];
#pragma unroll 8
        for (int gg = 0; gg < I3D; gg++) a += hc[b * I3D + gg] * W1[e * I3D + gg];
        h1[b * 64 + e] = gelu_f(a);
    }
    __syncthreads();
    for (int q = t; q < 4 * NN; q += 256) {
        int b = q / NN, n = q - b * NN;
        float a = b2[n];
#pragma unroll 8
        for (int e = 0; e < 64; e++) a += h1[b * 64 + e] * W2[n * 64 + e];
        out[b * NN + n] = a;
    }
}

// =====================================================================
// launcher
// =====================================================================
extern "C" void kernel_launch(void* const* d_in, const int* in_sizes, int n_in,
                              void* d_out, int out_size)
{
    const float* x     = (const float*)d_in[0];
    const float* ipW   = (const float*)d_in[1];
    const float* ipb   = (const float*)d_in[2];
    const float* fe    = (const float*)d_in[3];
    const float* te    = (const float*)d_in[4];
    const float* glW   = (const float*)d_in[5];
    const float* glb   = (const float*)d_in[6];
    const float* glg   = (const float*)d_in[7];
    const float* glbe  = (const float*)d_in[8];
    const float* Wih_s = (const float*)d_in[9];
    const float* Whh_s = (const float*)d_in[10];
    const float* bih_s = (const float*)d_in[11];
    const float* bhh_s = (const float*)d_in[12];
    const float* Wih_m = (const float*)d_in[13];
    const float* Whh_m = (const float*)d_in[14];
    const float* bih_m = (const float*)d_in[15];
    const float* bhh_m = (const float*)d_in[16];
    const float* Wih_l = (const float*)d_in[17];
    const float* Whh_l = (const float*)d_in[18];
    const float* bih_l = (const float*)d_in[19];
    const float* bhh_l = (const float*)d_in[20];
    const float* dhW1  = (const float*)d_in[21];
    const float* dhb1  = (const float*)d_in[22];
    const float* dhW2  = (const float*)d_in[23];
    const float* dhb2  = (const float*)d_in[24];
    float* out = (float*)d_out;

    k_input_proj<<<4000, 256>>>(x, ipW, ipb);
    k_adj<<<NN, 256>>>(fe, te);

    // layer 0
    k_agg_tc<<<dim3(4, GDCOL / 128), 256>>>();
    k_token_tc<<<4000, 256>>>(glW, glb, glg, glbe, 0);
    // layer 1
    k_agg_tc<<<dim3(4, GDCOL / 128), 256>>>();
    k_token_tc<<<4000, 256>>>(glW + 4096, glb + 64, glg + 64, glbe + 64, 1);

    // GRU input projections (split-K)
    k_xp<<<dim3(16, 3, SPLITK), 256>>>(Wih_l, 256, 1024, KCH_L, 0);
    k_xp<<<dim3(2, 3, SPLITK), 256>>>(Wih_m, 20, 80, KCH_L, 1);
    k_xp<<<dim3(1, 3, SPLITK), 256>>>(Wih_s, 10, 40, KCH_L, 2);
    k_xp_reduce<<<(1024 * I3D + 255) / 256, 256>>>(bih_l, 1024, 0);
    k_xp_reduce<<<(80 * I3D + 255) / 256, 256>>>(bih_m, 80, 1);
    k_xp_reduce<<<(40 * I3D + 255) / 256, 256>>>(bih_s, 40, 2);

    k_gru<<<12, 192>>>(Whh_s, bhh_s, Whh_m, bhh_m, Whh_l, bhh_l);
    k_head<<<1, 256>>>(dhW1, dhb1, dhW2, dhb2, out);
}